// round 1
// baseline (speedup 1.0000x reference)
#include <cuda_runtime.h>
#include <cstdint>

// ---------------------------------------------------------------------------
// KAN 2-layer fused evaluation.
//   x:     (128, 3072)
//   coef1: (256, 3072, 8)  sb1/ssp1: (256, 3072)
//   coef2: (10, 256, 8)    sb2/ssp2: (10, 256)
//   out:   (128, 10) fp32
//
// Reformulated as GEMMs over 9-wide per-input features:
//   f[b,i,:] = { silu(x[b,i]), B-spline basis_0..7(x[b,i]) }
//   W[o,i,:] = { sb[o,i], ssp[o,i]*coef[o,i,0..7] }
//   y[b,o]   = sum_{i,g} f[b,i,g] * W[o,i,g]
// ---------------------------------------------------------------------------

#define B_     128
#define IN_    3072
#define H_     256
#define OUT_   10
#define NF     9          // 1 silu + 8 basis

#define OTILE  32         // outputs per block (as 16 pairs)
#define KSPLIT 32         // k-splits over the 3072 input dim
#define IRANGE (IN_ / KSPLIT)   // 96 inputs per block
#define IC     4          // inputs staged per shared-memory chunk

// Scratch (static __device__ arrays: allocation-free per harness rules)
__device__ float4 g_F1[(IN_ * NF * B_) / 4];          // features, layout (i, g, b) — 14.2 MB
__device__ float  g_Y1p[KSPLIT * B_ * H_];            // layer-1 partials per split — 4 MB

// ---------------------------------------------------------------------------
// Activations + cubic B-spline basis (num=5, k=3 → 12 knots on [-2.2, 2.2])
// ---------------------------------------------------------------------------
__device__ __forceinline__ float silu_f(float x) {
    return x / (1.0f + __expf(-x));
}

__device__ __forceinline__ float selu_f(float x) {
    const float scale = 1.0507009873554805f;
    const float alpha = 1.6732632423543772f;
    return x > 0.0f ? scale * x : scale * alpha * expm1f(x);
}

__device__ __forceinline__ void features9(float x, float f[NF]) {
    f[0] = silu_f(x);
    // Cox-de Boor recursion, uniform knots t_j = -2.2 + 0.4*j, j = 0..11
    float bb[11];
#pragma unroll
    for (int j = 0; j < 11; j++) {
        float tj  = -2.2f + 0.4f * j;
        float tj1 = -2.2f + 0.4f * (j + 1);
        bb[j] = (x >= tj && x < tj1) ? 1.0f : 0.0f;
    }
#pragma unroll
    for (int d = 1; d <= 3; d++) {
        float inv = 1.0f / (0.4f * d);
#pragma unroll 10
        for (int j = 0; j <= 10 - d; j++) {
            float tj   = -2.2f + 0.4f * j;
            float tjd1 = -2.2f + 0.4f * (j + d + 1);
            bb[j] = (x - tj) * inv * bb[j] + (tjd1 - x) * inv * bb[j + 1];
        }
    }
#pragma unroll
    for (int g = 0; g < 8; g++) f[1 + g] = bb[g];
}

// ---------------------------------------------------------------------------
// K1: features for layer 1.  F1[(i*9 + g)*128 + b] = f_g(x[b,i])
// ---------------------------------------------------------------------------
__global__ void __launch_bounds__(256) k1_features(const float* __restrict__ x) {
    int tid = blockIdx.x * 256 + threadIdx.x;   // 0 .. 128*3072-1
    int b = tid & (B_ - 1);
    int i = tid >> 7;
    float xv = x[b * IN_ + i];
    float f[NF];
    features9(xv, f);
    float* F = (float*)g_F1;
#pragma unroll
    for (int g = 0; g < NF; g++) F[(i * NF + g) * B_ + b] = f[g];
}

// ---------------------------------------------------------------------------
// K2: layer-1 GEMM, partials per k-split.
// Grid: (8 o-tiles, 32 k-splits). Block: 256 threads.
// Thread = (o-pair = tid/16, b-group of 8 = tid%16), 16 fp32 accumulators.
// ---------------------------------------------------------------------------
__global__ void __launch_bounds__(256) k2_layer1(const float* __restrict__ coef1,
                                                const float* __restrict__ sb1,
                                                const float* __restrict__ ssp1) {
    __shared__ float4 Fs[IC * NF * (B_ / 4)];                 // [i][g][b/4]  18 KB
    __shared__ __align__(16) float Ws[OTILE * IC * 12];       // [o][i][12]    6 KB

    const int tid    = threadIdx.x;
    const int otile  = blockIdx.x;
    const int split  = blockIdx.y;
    const int i0     = split * IRANGE;
    const int ogbase = otile * OTILE;

    const int op = tid >> 4;   // 0..15 -> outputs (2*op, 2*op+1)
    const int bg = tid & 15;   // 0..15 -> batch rows bg*8 .. bg*8+7

    float acc0[8], acc1[8];
#pragma unroll
    for (int j = 0; j < 8; j++) { acc0[j] = 0.0f; acc1[j] = 0.0f; }

    // Per-chunk W staging indices (hoisted)
    const int wo_l = tid >> 3;          // 0..31
    const int wq   = tid & 7;           // 0..7
    const int wi_l = wq >> 1;           // 0..3
    const int wgp  = (wq & 1) * 4;
    const int wog  = ogbase + wo_l;

    for (int ic = 0; ic < IRANGE; ic += IC) {
        const int ibase = i0 + ic;

        // --- stage features: contiguous 4*9*128 floats ---
        const float4* Fsrc = g_F1 + ibase * NF * (B_ / 4);
#pragma unroll
        for (int idx = tid; idx < IC * NF * (B_ / 4); idx += 256) Fs[idx] = Fsrc[idx];

        // --- stage fused weights W[o][i][0..8] (12-padded) ---
        {
            int irow = wog * IN_ + ibase + wi_l;
            float4 cv = ((const float4*)coef1)[irow * 2 + (wq & 1)];
            float  sp = ssp1[irow];
            float* wd = &Ws[(wo_l * IC + wi_l) * 12 + 1 + wgp];
            wd[0] = sp * cv.x; wd[1] = sp * cv.y; wd[2] = sp * cv.z; wd[3] = sp * cv.w;
        }
        if (tid < 128) {
            int o_l = tid >> 2, i_l = tid & 3;
            Ws[(o_l * IC + i_l) * 12] = sb1[(ogbase + o_l) * IN_ + ibase + i_l];
        }
        __syncthreads();

        const float4* W4 = (const float4*)Ws;
#pragma unroll
        for (int il = 0; il < IC; il++) {
            float w0[NF], w1[NF];
            {
                float4 a = W4[((2 * op)     * IC + il) * 3 + 0];
                float4 b4= W4[((2 * op)     * IC + il) * 3 + 1];
                float4 c = W4[((2 * op)     * IC + il) * 3 + 2];
                w0[0]=a.x; w0[1]=a.y; w0[2]=a.z; w0[3]=a.w;
                w0[4]=b4.x; w0[5]=b4.y; w0[6]=b4.z; w0[7]=b4.w; w0[8]=c.x;
            }
            {
                float4 a = W4[((2 * op + 1) * IC + il) * 3 + 0];
                float4 b4= W4[((2 * op + 1) * IC + il) * 3 + 1];
                float4 c = W4[((2 * op + 1) * IC + il) * 3 + 2];
                w1[0]=a.x; w1[1]=a.y; w1[2]=a.z; w1[3]=a.w;
                w1[4]=b4.x; w1[5]=b4.y; w1[6]=b4.z; w1[7]=b4.w; w1[8]=c.x;
            }
#pragma unroll
            for (int g = 0; g < NF; g++) {
                float4 fa = Fs[(il * NF + g) * (B_ / 4) + bg * 2];
                float4 fb = Fs[(il * NF + g) * (B_ / 4) + bg * 2 + 1];
                acc0[0] += w0[g] * fa.x;  acc0[1] += w0[g] * fa.y;
                acc0[2] += w0[g] * fa.z;  acc0[3] += w0[g] * fa.w;
                acc0[4] += w0[g] * fb.x;  acc0[5] += w0[g] * fb.y;
                acc0[6] += w0[g] * fb.z;  acc0[7] += w0[g] * fb.w;
                acc1[0] += w1[g] * fa.x;  acc1[1] += w1[g] * fa.y;
                acc1[2] += w1[g] * fa.z;  acc1[3] += w1[g] * fa.w;
                acc1[4] += w1[g] * fb.x;  acc1[5] += w1[g] * fb.y;
                acc1[6] += w1[g] * fb.z;  acc1[7] += w1[g] * fb.w;
            }
        }
        __syncthreads();
    }

    // --- write partials: g_Y1p[split][b][o] ---
    float* Yout = g_Y1p + split * (B_ * H_);
    const int o0 = ogbase + 2 * op;
    const int b0 = bg * 8;
#pragma unroll
    for (int j = 0; j < 8; j++) {
        Yout[(b0 + j) * H_ + o0    ] = acc0[j];
        Yout[(b0 + j) * H_ + o0 + 1] = acc1[j];
    }
}

// ---------------------------------------------------------------------------
// K3: split-reduce + selu + layer-2 (features, 10-wide dot, block reduce)
// Grid: 128 blocks (one per batch row), 256 threads (one per hidden unit).
// ---------------------------------------------------------------------------
__global__ void __launch_bounds__(256) k3_layer2(const float* __restrict__ coef2,
                                                const float* __restrict__ sb2,
                                                const float* __restrict__ ssp2,
                                                float* __restrict__ out) {
    const int b = blockIdx.x;
    const int t = threadIdx.x;

    float y = 0.0f;
#pragma unroll
    for (int s = 0; s < KSPLIT; s++) y += g_Y1p[(s * B_ + b) * H_ + t];

    float h = selu_f(y);
    float f[NF];
    features9(h, f);

    __shared__ float red[OUT_ * 256];
#pragma unroll
    for (int o = 0; o < OUT_; o++) {
        int e = o * H_ + t;
        float4 c0 = ((const float4*)coef2)[e * 2];
        float4 c1 = ((const float4*)coef2)[e * 2 + 1];
        float sp = ssp2[e];
        float spline = f[1] * c0.x + f[2] * c0.y + f[3] * c0.z + f[4] * c0.w
                     + f[5] * c1.x + f[6] * c1.y + f[7] * c1.z + f[8] * c1.w;
        red[o * 256 + t] = sb2[e] * f[0] + sp * spline;
    }
    __syncthreads();

    for (int s = 128; s > 0; s >>= 1) {
        if (t < s) {
#pragma unroll
            for (int o = 0; o < OUT_; o++) red[o * 256 + t] += red[o * 256 + t + s];
        }
        __syncthreads();
    }
    if (t < OUT_) out[b * OUT_ + t] = red[t * 256];
}

// ---------------------------------------------------------------------------
extern "C" void kernel_launch(void* const* d_in, const int* in_sizes, int n_in,
                              void* d_out, int out_size) {
    const float* x     = (const float*)d_in[0];
    const float* coef1 = (const float*)d_in[1];
    const float* sb1   = (const float*)d_in[2];
    const float* ssp1  = (const float*)d_in[3];
    const float* coef2 = (const float*)d_in[4];
    const float* sb2   = (const float*)d_in[5];
    const float* ssp2  = (const float*)d_in[6];
    float* out = (float*)d_out;

    k1_features<<<(B_ * IN_) / 256, 256>>>(x);
    k2_layer1<<<dim3(H_ / OTILE, KSPLIT), 256>>>(coef1, sb1, ssp1);
    k3_layer2<<<B_, 256>>>(coef2, sb2, ssp2, out);
}

// round 2
// speedup vs baseline: 2.1590x; 2.1590x over previous
#include <cuda_runtime.h>
#include <cstdint>

// ---------------------------------------------------------------------------
// KAN 2-layer fused evaluation (round 2: f32x2 packed FMA + conflict-free smem)
//   x:(128,3072)  coef1:(256,3072,8) sb1/ssp1:(256,3072)
//   coef2:(10,256,8) sb2/ssp2:(10,256)  out:(128,10) fp32
//
// Layer 1 as GEMM over 9-wide features f = {silu(x), basis_0..7(x)},
// fused weights W[o,i,:] = {sb, ssp*coef}.  M=128(b) N=256(o) K=3072*9.
// ---------------------------------------------------------------------------

#define B_     128
#define IN_    3072
#define H_     256
#define OUT_   10
#define NF     9

#define OTILE  64               // outputs per block
#define KSPLIT 64               // splits over input dim
#define IRANGE (IN_ / KSPLIT)   // 48 inputs per block
#define IC     4                // inputs per smem chunk

typedef unsigned long long ull;

__device__ float4 g_F1[(IN_ * NF * B_) / 4];     // features (i, g, b) — 14.2 MB
__device__ float  g_Y1p[KSPLIT * B_ * H_];       // layer-1 partials — 8 MB

// ---- packed fp32x2 helpers (sm_100a) --------------------------------------
__device__ __forceinline__ ull fma2(ull a, ull b, ull c) {
    ull d;
    asm("fma.rn.f32x2 %0, %1, %2, %3;" : "=l"(d) : "l"(a), "l"(b), "l"(c));
    return d;
}
__device__ __forceinline__ ull pack2(float w) {
    ull d;
    asm("mov.b64 %0, {%1, %1};" : "=l"(d) : "r"(__float_as_uint(w)));
    return d;
}
__device__ __forceinline__ float lo32(ull a) { return __uint_as_float((unsigned)a); }
__device__ __forceinline__ float hi32(ull a) { return __uint_as_float((unsigned)(a >> 32)); }

// ---- activations + cubic B-spline basis (num=5,k=3: knots -2.2..2.2) ------
__device__ __forceinline__ float silu_f(float x) { return x / (1.0f + __expf(-x)); }

__device__ __forceinline__ float selu_f(float x) {
    const float scale = 1.0507009873554805f;
    const float alpha = 1.6732632423543772f;
    return x > 0.0f ? scale * x : scale * alpha * expm1f(x);
}

__device__ __forceinline__ void features9(float x, float f[NF]) {
    f[0] = silu_f(x);
    float bb[11];
#pragma unroll
    for (int j = 0; j < 11; j++) {
        float tj  = -2.2f + 0.4f * j;
        float tj1 = -2.2f + 0.4f * (j + 1);
        bb[j] = (x >= tj && x < tj1) ? 1.0f : 0.0f;
    }
#pragma unroll
    for (int d = 1; d <= 3; d++) {
        float inv = 1.0f / (0.4f * d);
#pragma unroll 10
        for (int j = 0; j <= 10 - d; j++) {
            float tj   = -2.2f + 0.4f * j;
            float tjd1 = -2.2f + 0.4f * (j + d + 1);
            bb[j] = (x - tj) * inv * bb[j] + (tjd1 - x) * inv * bb[j + 1];
        }
    }
#pragma unroll
    for (int g = 0; g < 8; g++) f[1 + g] = bb[g];
}

// ---------------------------------------------------------------------------
// K1: features.  F1[(i*9+g)*128 + b] = f_g(x[b,i])
// ---------------------------------------------------------------------------
__global__ void __launch_bounds__(256) k1_features(const float* __restrict__ x) {
    int tid = blockIdx.x * 256 + threadIdx.x;
    int b = tid & (B_ - 1);
    int i = tid >> 7;
    float f[NF];
    features9(x[b * IN_ + i], f);
    float* F = (float*)g_F1;
#pragma unroll
    for (int g = 0; g < NF; g++) F[(i * NF + g) * B_ + b] = f[g];
}

// ---------------------------------------------------------------------------
// K2: layer-1 GEMM with f32x2 packed accumulation.
// Grid (H/OTILE=4, KSPLIT=64), block 256.
// Thread = (oq = tid>>4: 4 outputs 4oq..4oq+3, bg = tid&15: 8 batch rows
//           {4bg..4bg+3} and {64+4bg..64+4bg+3}).
// ---------------------------------------------------------------------------
__global__ void __launch_bounds__(256) k2_layer1(const float* __restrict__ coef1,
                                                const float* __restrict__ sb1,
                                                const float* __restrict__ ssp1) {
    __shared__ float4 Fs[IC * NF * (B_ / 4)];            // [i][g][b/4]  18 KB
    __shared__ __align__(16) float Ws[OTILE * IC * 12];  // [o][i][12]   12 KB
    // Ws layout per (o,i): [0]=sb, [4..11]=ssp*coef[0..7], rest pad.

    const int tid    = threadIdx.x;
    const int ogbase = blockIdx.x * OTILE;
    const int i0     = blockIdx.y * IRANGE;

    const int oq = tid >> 4;     // 0..15
    const int bg = tid & 15;     // 0..15

    ull acc[4][4];
#pragma unroll
    for (int o = 0; o < 4; o++)
#pragma unroll
        for (int p = 0; p < 4; p++) acc[o][p] = 0ull;

    // staging index: one thread per (o_l, i_l)
    const int so = tid >> 2;     // 0..63
    const int si = tid & 3;      // 0..3

    const ulonglong2* FsU = reinterpret_cast<const ulonglong2*>(Fs);

    for (int ic = 0; ic < IRANGE; ic += IC) {
        const int ibase = i0 + ic;

        // stage features (contiguous 1152 float4)
        const float4* Fsrc = g_F1 + ibase * NF * (B_ / 4);
        for (int idx = tid; idx < IC * NF * (B_ / 4); idx += 256) Fs[idx] = Fsrc[idx];

        // stage fused weights: thread (so, si)
        {
            int irow = (ogbase + so) * IN_ + ibase + si;
            float4 c0 = ((const float4*)coef1)[irow * 2];
            float4 c1 = ((const float4*)coef1)[irow * 2 + 1];
            float  sp = ssp1[irow];
            float* wd = &Ws[(so * IC + si) * 12];
            wd[0] = sb1[irow];
            ((float4*)(wd + 4))[0] = make_float4(sp * c0.x, sp * c0.y, sp * c0.z, sp * c0.w);
            ((float4*)(wd + 8))[0] = make_float4(sp * c1.x, sp * c1.y, sp * c1.z, sp * c1.w);
        }
        __syncthreads();

#pragma unroll
        for (int il = 0; il < IC; il++) {
            float w[4][NF];
#pragma unroll
            for (int o = 0; o < 4; o++) {
                const float4* Wp = (const float4*)&Ws[((4 * oq + o) * IC + il) * 12];
                float4 A = Wp[0], Bv = Wp[1], C = Wp[2];
                w[o][0] = A.x;
                w[o][1] = Bv.x; w[o][2] = Bv.y; w[o][3] = Bv.z; w[o][4] = Bv.w;
                w[o][5] = C.x;  w[o][6] = C.y;  w[o][7] = C.z;  w[o][8] = C.w;
            }
#pragma unroll
            for (int g = 0; g < NF; g++) {
                ulonglong2 fa = FsU[(il * NF + g) * 32 + bg];        // b 4bg..4bg+3
                ulonglong2 fb = FsU[(il * NF + g) * 32 + 16 + bg];   // b 64+4bg..
#pragma unroll
                for (int o = 0; o < 4; o++) {
                    ull wp = pack2(w[o][g]);
                    acc[o][0] = fma2(wp, fa.x, acc[o][0]);
                    acc[o][1] = fma2(wp, fa.y, acc[o][1]);
                    acc[o][2] = fma2(wp, fb.x, acc[o][2]);
                    acc[o][3] = fma2(wp, fb.y, acc[o][3]);
                }
            }
        }
        __syncthreads();
    }

    // write partials: g_Y1p[split][b][o], float4 across the 4 o's
    float* Yout = g_Y1p + blockIdx.y * (B_ * H_);
    const int o0 = ogbase + 4 * oq;
#pragma unroll
    for (int half = 0; half < 2; half++) {
#pragma unroll
        for (int j = 0; j < 4; j++) {
            int b = half * 64 + 4 * bg + j;
            int p = half * 2 + (j >> 1);
            float4 v;
            if (j & 1) v = make_float4(hi32(acc[0][p]), hi32(acc[1][p]), hi32(acc[2][p]), hi32(acc[3][p]));
            else       v = make_float4(lo32(acc[0][p]), lo32(acc[1][p]), lo32(acc[2][p]), lo32(acc[3][p]));
            *(float4*)&Yout[b * H_ + o0] = v;
        }
    }
}

// ---------------------------------------------------------------------------
// K3: split-reduce + selu + layer-2. Grid 128 (batch), block 256 (hidden).
// ---------------------------------------------------------------------------
__global__ void __launch_bounds__(256) k3_layer2(const float* __restrict__ coef2,
                                                const float* __restrict__ sb2,
                                                const float* __restrict__ ssp2,
                                                float* __restrict__ out) {
    const int b = blockIdx.x;
    const int t = threadIdx.x;

    float y = 0.0f;
#pragma unroll
    for (int s = 0; s < KSPLIT; s++) y += g_Y1p[(s * B_ + b) * H_ + t];

    float h = selu_f(y);
    float f[NF];
    features9(h, f);

    __shared__ float red[OUT_ * 256];
#pragma unroll
    for (int o = 0; o < OUT_; o++) {
        int e = o * H_ + t;
        float4 c0 = ((const float4*)coef2)[e * 2];
        float4 c1 = ((const float4*)coef2)[e * 2 + 1];
        float sp = ssp2[e];
        float spline = f[1] * c0.x + f[2] * c0.y + f[3] * c0.z + f[4] * c0.w
                     + f[5] * c1.x + f[6] * c1.y + f[7] * c1.z + f[8] * c1.w;
        red[o * 256 + t] = sb2[e] * f[0] + sp * spline;
    }
    __syncthreads();

    for (int s = 128; s > 0; s >>= 1) {
        if (t < s) {
#pragma unroll
            for (int o = 0; o < OUT_; o++) red[o * 256 + t] += red[o * 256 + t + s];
        }
        __syncthreads();
    }
    if (t < OUT_) out[b * OUT_ + t] = red[t * 256];
}

// ---------------------------------------------------------------------------
extern "C" void kernel_launch(void* const* d_in, const int* in_sizes, int n_in,
                              void* d_out, int out_size) {
    const float* x     = (const float*)d_in[0];
    const float* coef1 = (const float*)d_in[1];
    const float* sb1   = (const float*)d_in[2];
    const float* ssp1  = (const float*)d_in[3];
    const float* coef2 = (const float*)d_in[4];
    const float* sb2   = (const float*)d_in[5];
    const float* ssp2  = (const float*)d_in[6];
    float* out = (float*)d_out;

    k1_features<<<(B_ * IN_) / 256, 256>>>(x);
    k2_layer1<<<dim3(H_ / OTILE, KSPLIT), 256>>>(coef1, sb1, ssp1);
    k3_layer2<<<B_, 256>>>(coef2, sb2, ssp2, out);
}

// round 4
// speedup vs baseline: 4.0156x; 1.8600x over previous
#include <cuda_runtime.h>
#include <cstdint>

// ---------------------------------------------------------------------------
// KAN 2-layer fused, round 4: layer-1 GEMM on warp-level mma.sync (tf32).
// (tcgen05 is unavailable: harness PTX target is baseline sm_100, no 'a'.)
//
//   D[o,b] = sum_{i,g} W[o,i,g] * f_g(x[b,i])
//   f = {basis_0..7(x), silu(x)},  W = {ssp*coef_0..7, sb}   (9 K per input)
//   per CTA: M=128 (o), N=128 (b), K=432;  grid (2 o-tiles, 64 k-splits)
// ---------------------------------------------------------------------------

#define B_     128
#define IN_    3072
#define H_     256
#define OUT_   10
#define KSPLIT 64
#define IPC    48          // inputs per CTA
#define NCH    6           // chunks of 8 inputs
#define NKS    9           // k-steps (of 8) per chunk: 8 inputs * 9 feats = 72

__device__ float g_Y1p[KSPLIT * B_ * H_];    // layer-1 partials [split][b][o]

// ---- dynamic smem layout ---------------------------------------------------
#define XS_PITCH 49
#define SM_XS    0                           // x slab: 128*49*4 = 25088 B
#define SM_A0    25088                       // A tile: 9*8*32*4*4  = 36864 B
#define SM_B0    (SM_A0 + 36864)             // B tile: 9*16*32*2*4 = 36864 B
#define SM_A1    (SM_B0 + 36864)
#define SM_B1    (SM_A1 + 36864)
#define SMEM_TOTAL (SM_B1 + 36864)           // 172544 B
#define SP       132                         // writeout transpose pitch

// ---- helpers ---------------------------------------------------------------
__device__ __forceinline__ uint32_t tf32r(float x) {     // round-to-nearest tf32
    uint32_t r;
    asm("cvt.rna.tf32.f32 %0, %1;" : "=r"(r) : "f"(x));
    return r;
}
__device__ __forceinline__ void mma8(float d[4], const uint32_t a[4], const uint32_t b[2]) {
    asm volatile("mma.sync.aligned.m16n8k8.row.col.f32.tf32.tf32.f32 "
        "{%0,%1,%2,%3}, {%4,%5,%6,%7}, {%8,%9}, {%0,%1,%2,%3};"
        : "+f"(d[0]), "+f"(d[1]), "+f"(d[2]), "+f"(d[3])
        : "r"(a[0]), "r"(a[1]), "r"(a[2]), "r"(a[3]), "r"(b[0]), "r"(b[1]));
}
__device__ __forceinline__ float silu_f(float x) { return x / (1.0f + __expf(-x)); }
__device__ __forceinline__ float selu_f(float x) {
    const float scale = 1.0507009873554805f;
    const float alpha = 1.6732632423543772f;
    return x > 0.0f ? scale * x : scale * alpha * expm1f(x);
}
__device__ __forceinline__ void basis8(float x, float f[8]) {
    float bb[11];
#pragma unroll
    for (int j = 0; j < 11; j++) {
        float tj  = -2.2f + 0.4f * j;
        float tj1 = -2.2f + 0.4f * (j + 1);
        bb[j] = (x >= tj && x < tj1) ? 1.0f : 0.0f;
    }
#pragma unroll
    for (int d = 1; d <= 3; d++) {
        float inv = 1.0f / (0.4f * d);
#pragma unroll 10
        for (int j = 0; j <= 10 - d; j++) {
            float tj   = -2.2f + 0.4f * j;
            float tjd1 = -2.2f + 0.4f * (j + d + 1);
            bb[j] = (x - tj) * inv * bb[j] + (tjd1 - x) * inv * bb[j + 1];
        }
    }
#pragma unroll
    for (int g = 0; g < 8; g++) f[g] = bb[g];
}

// Fragment-slot scatter addresses (floats):
//   A_s[ks][mt(8)][lane(32)][word(4)]  word = (kc>=4)*2 + (r16>=8), lane=(r16&7)*4+(kc&3)
//   B_s[ks][nt(16)][lane(32)][word(2)] word = kc>>2,                lane=(b&7)*4+(kc&3)

// ---------------------------------------------------------------------------
__global__ void __launch_bounds__(256, 1) k2_mma(const float* __restrict__ x,
                                                const float* __restrict__ coef1,
                                                const float* __restrict__ sb1,
                                                const float* __restrict__ ssp1) {
    extern __shared__ __align__(16) char smem[];
    float* xs = (float*)(smem + SM_XS);

    const int tid  = threadIdx.x;
    const int lane = tid & 31;
    const int wid  = tid >> 5;
    const int wm   = wid >> 2;          // 0..1  (o: 64 per warp)
    const int wn   = wid & 3;           // 0..3  (b: 32 per warp)
    const int o0   = blockIdx.x * 128;
    const int split = blockIdx.y;
    const int i0   = split * IPC;

    // stage x slab
    for (int idx = tid; idx < B_ * IPC; idx += 256) {
        int b = idx / IPC, c = idx % IPC;
        xs[b * XS_PITCH + c] = x[b * IN_ + i0 + c];
    }

    float acc[4][4][4];
#pragma unroll
    for (int mi = 0; mi < 4; mi++)
#pragma unroll
        for (int ni = 0; ni < 4; ni++)
#pragma unroll
            for (int w = 0; w < 4; w++) acc[mi][ni][w] = 0.0f;

    // per-thread producer assignment: 4 edges (o_l, ii) per chunk
    float4 pc0[4], pc1[4];
    float  psp[4], psb[4];

    auto ldgA = [&](int ib) {
#pragma unroll
        for (int p = 0; p < 4; p++) {
            int q = tid + 256 * p;
            int o_l = q >> 3, ii = q & 7;
            int e = (o0 + o_l) * IN_ + ib + ii;
            pc0[p] = ((const float4*)coef1)[e * 2];
            pc1[p] = ((const float4*)coef1)[e * 2 + 1];
            psp[p] = ssp1[e];
            psb[p] = sb1[e];
        }
    };
    auto stsA = [&](uint32_t offA) {
        uint32_t* As = (uint32_t*)(smem + offA);
#pragma unroll
        for (int p = 0; p < 4; p++) {
            int q = tid + 256 * p;
            int o_l = q >> 3, ii = q & 7;
            float v[9] = { psp[p] * pc0[p].x, psp[p] * pc0[p].y, psp[p] * pc0[p].z,
                           psp[p] * pc0[p].w, psp[p] * pc1[p].x, psp[p] * pc1[p].y,
                           psp[p] * pc1[p].z, psp[p] * pc1[p].w, psb[p] };
            int mt = o_l >> 4, r = o_l & 15;
#pragma unroll
            for (int g = 0; g < 9; g++) {
                int kk = ii * 9 + g, ks = kk >> 3, kc = kk & 7;
                int idx = ((ks * 8 + mt) * 32 + (r & 7) * 4 + (kc & 3)) * 4
                          + ((kc >> 2) << 1) + (r >> 3);
                As[idx] = tf32r(v[g]);
            }
        }
    };
    auto prodB = [&](int coff, uint32_t offB) {
        uint32_t* Bs = (uint32_t*)(smem + offB);
#pragma unroll
        for (int p = 0; p < 4; p++) {
            int q = tid + 256 * p;
            int b = q & 127, ii = q >> 7;
            float xv = xs[b * XS_PITCH + coff + ii];
            float f[9];
            basis8(xv, f);
            f[8] = silu_f(xv);
            int nt = b >> 3, ln = (b & 7) * 4;
#pragma unroll
            for (int g = 0; g < 9; g++) {
                int kk = ii * 9 + g, ks = kk >> 3, kc = kk & 7;
                int idx = ((ks * 16 + nt) * 32 + ln + (kc & 3)) * 2 + (kc >> 2);
                Bs[idx] = tf32r(f[g]);
            }
        }
    };
    auto consume = [&](uint32_t offA, uint32_t offB) {
        const float4* As = (const float4*)(smem + offA);   // 16B per (ks,mt,lane)
        const float2* Bs = (const float2*)(smem + offB);   // 8B per (ks,nt,lane)
#pragma unroll
        for (int ks = 0; ks < NKS; ks++) {
            uint32_t af[4][4], bf[4][2];
#pragma unroll
            for (int mi = 0; mi < 4; mi++) {
                float4 v = As[(ks * 8 + wm * 4 + mi) * 32 + lane];
                af[mi][0] = __float_as_uint(v.x); af[mi][1] = __float_as_uint(v.y);
                af[mi][2] = __float_as_uint(v.z); af[mi][3] = __float_as_uint(v.w);
            }
#pragma unroll
            for (int ni = 0; ni < 4; ni++) {
                float2 v = Bs[(ks * 16 + wn * 4 + ni) * 32 + lane];
                bf[ni][0] = __float_as_uint(v.x); bf[ni][1] = __float_as_uint(v.y);
            }
#pragma unroll
            for (int mi = 0; mi < 4; mi++)
#pragma unroll
                for (int ni = 0; ni < 4; ni++) mma8(acc[mi][ni], af[mi], bf[ni]);
        }
    };

    // --- pipeline: produce(0); loop { ldgA(t+1); consume(t); sts(t+1); sync } ---
    ldgA(i0);
    __syncthreads();                 // xs ready (needed by prodB)
    prodB(0, SM_B0);
    stsA(SM_A0);
    __syncthreads();

    for (int t = 0; t < NCH; t++) {
        const uint32_t offA = (t & 1) ? SM_A1 : SM_A0;
        const uint32_t offB = (t & 1) ? SM_B1 : SM_B0;
        const uint32_t nfA  = (t & 1) ? SM_A0 : SM_A1;
        const uint32_t nfB  = (t & 1) ? SM_B0 : SM_B1;
        if (t + 1 < NCH) ldgA(i0 + (t + 1) * 8);
        consume(offA, offB);
        if (t + 1 < NCH) { stsA(nfA); prodB((t + 1) * 8, nfB); }
        __syncthreads();
    }

    // --- writeout: transpose through smem, coalesced float4 partial stores ---
    {
        float* S = (float*)(smem + SM_A0);          // [128 b][pitch SP]
        const int r = lane >> 2, c = lane & 3;
#pragma unroll
        for (int mi = 0; mi < 4; mi++)
#pragma unroll
            for (int ni = 0; ni < 4; ni++)
#pragma unroll
                for (int w = 0; w < 4; w++) {
                    int o_l = (wm * 4 + mi) * 16 + r + 8 * (w >> 1);
                    int b_l = (wn * 4 + ni) * 8 + 2 * c + (w & 1);
                    S[b_l * SP + o_l] = acc[mi][ni][w];
                }
        __syncthreads();
        float* Y = g_Y1p + split * (B_ * H_);
#pragma unroll
        for (int p = 0; p < 16; p++) {
            int idx = tid + 256 * p;
            int bb = idx >> 5, o4 = idx & 31;
            float4 v = *(float4*)&S[bb * SP + o4 * 4];
            *(float4*)&Y[bb * H_ + o0 + o4 * 4] = v;
        }
    }
}

// ---------------------------------------------------------------------------
// K3: split-reduce + selu + layer-2 (validated in rounds 1-2).
// ---------------------------------------------------------------------------
__global__ void __launch_bounds__(256) k3_layer2(const float* __restrict__ coef2,
                                                const float* __restrict__ sb2,
                                                const float* __restrict__ ssp2,
                                                float* __restrict__ out) {
    const int b = blockIdx.x;
    const int t = threadIdx.x;

    float y = 0.0f;
#pragma unroll
    for (int s = 0; s < KSPLIT; s++) y += g_Y1p[(s * B_ + b) * H_ + t];

    float h = selu_f(y);
    float f[9];
    f[0] = silu_f(h);
    basis8(h, f + 1);

    __shared__ float red[OUT_ * 256];
#pragma unroll
    for (int o = 0; o < OUT_; o++) {
        int e = o * H_ + t;
        float4 c0 = ((const float4*)coef2)[e * 2];
        float4 c1 = ((const float4*)coef2)[e * 2 + 1];
        float sp = ssp2[e];
        float spline = f[1] * c0.x + f[2] * c0.y + f[3] * c0.z + f[4] * c0.w
                     + f[5] * c1.x + f[6] * c1.y + f[7] * c1.z + f[8] * c1.w;
        red[o * 256 + t] = sb2[e] * f[0] + sp * spline;
    }
    __syncthreads();

    for (int s = 128; s > 0; s >>= 1) {
        if (t < s) {
#pragma unroll
            for (int o = 0; o < OUT_; o++) red[o * 256 + t] += red[o * 256 + t + s];
        }
        __syncthreads();
    }
    if (t < OUT_) out[b * OUT_ + t] = red[t * 256];
}

// ---------------------------------------------------------------------------
extern "C" void kernel_launch(void* const* d_in, const int* in_sizes, int n_in,
                              void* d_out, int out_size) {
    const float* x     = (const float*)d_in[0];
    const float* coef1 = (const float*)d_in[1];
    const float* sb1   = (const float*)d_in[2];
    const float* ssp1  = (const float*)d_in[3];
    const float* coef2 = (const float*)d_in[4];
    const float* sb2   = (const float*)d_in[5];
    const float* ssp2  = (const float*)d_in[6];
    float* out = (float*)d_out;

    cudaFuncSetAttribute(k2_mma, cudaFuncAttributeMaxDynamicSharedMemorySize, SMEM_TOTAL);
    k2_mma<<<dim3(2, KSPLIT), 256, SMEM_TOTAL>>>(x, coef1, sb1, ssp1);
    k3_layer2<<<B_, 256>>>(coef2, sb2, ssp2, out);
}

// round 5
// speedup vs baseline: 4.2561x; 1.0599x over previous
#include <cuda_runtime.h>
#include <cstdint>

// ---------------------------------------------------------------------------
// KAN 2-layer fused, round 5: mma.sync tf32 layer-1 + closed-form B-spline
// + high-parallelism split reduction.
//   D[o,b] = sum_{i,g} W[o,i,g] * f_g(x[b,i])
//   f = {basis_0..7(x), silu(x)},  W = {ssp*coef_0..7, sb}   (9 K per input)
//   K2: per CTA M=128 (o), N=128 (b), K=432;  grid (2 o-tiles, 64 k-splits)
// ---------------------------------------------------------------------------

#define B_     128
#define IN_    3072
#define H_     256
#define OUT_   10
#define KSPLIT 64
#define IPC    48          // inputs per CTA
#define NCH    6           // chunks of 8 inputs
#define NKS    9           // k-steps (of 8) per chunk: 8 inputs * 9 feats = 72

__device__ float g_Y1p[KSPLIT * B_ * H_];    // layer-1 partials [split][b][o]
__device__ float g_Y1[B_ * H_];              // reduced layer-1 pre-activation

// ---- dynamic smem layout ---------------------------------------------------
#define XS_PITCH 49
#define SM_XS    0
#define SM_A0    25088
#define SM_B0    (SM_A0 + 36864)
#define SM_A1    (SM_B0 + 36864)
#define SM_B1    (SM_A1 + 36864)
#define SMEM_TOTAL (SM_B1 + 36864)
#define SP       132

// ---- helpers ---------------------------------------------------------------
__device__ __forceinline__ uint32_t tf32r(float x) {
    uint32_t r;
    asm("cvt.rna.tf32.f32 %0, %1;" : "=r"(r) : "f"(x));
    return r;
}
__device__ __forceinline__ void mma8(float d[4], const uint32_t a[4], const uint32_t b[2]) {
    asm volatile("mma.sync.aligned.m16n8k8.row.col.f32.tf32.tf32.f32 "
        "{%0,%1,%2,%3}, {%4,%5,%6,%7}, {%8,%9}, {%0,%1,%2,%3};"
        : "+f"(d[0]), "+f"(d[1]), "+f"(d[2]), "+f"(d[3])
        : "r"(a[0]), "r"(a[1]), "r"(a[2]), "r"(a[3]), "r"(b[0]), "r"(b[1]));
}
__device__ __forceinline__ float silu_f(float x) { return x / (1.0f + __expf(-x)); }
__device__ __forceinline__ float selu_f(float x) {
    const float scale = 1.0507009873554805f;
    const float alpha = 1.6732632423543772f;
    return x > 0.0f ? scale * x : scale * alpha * expm1f(x);
}

// Closed-form cubic B-spline on uniform extended grid t_j = -2.2 + 0.4 j
// (j=0..11). For x in [t_m, t_m+1), nonzero cubics are indices m-3..m with
// the cardinal weights below (== Cox-de-Boor recursion analytically).
struct Bsp { float w0, w1, w2, w3; int m; };
__device__ __forceinline__ Bsp bspline4(float x) {
    Bsp r;
    float tpos = (x + 2.2f) * 2.5f;
    float mf = floorf(tpos);
    r.m = (int)mf;
    float u = tpos - mf;
    float u2 = u * u, u3 = u2 * u, om = 1.0f - u;
    bool valid = (x >= -2.2f) && (r.m <= 10);
    float s = valid ? (1.0f / 6.0f) : 0.0f;
    r.w0 = om * om * om * s;
    r.w1 = (3.0f * u3 - 6.0f * u2 + 4.0f) * s;
    r.w2 = (-3.0f * u3 + 3.0f * u2 + 3.0f * u + 1.0f) * s;
    r.w3 = u3 * s;
    return r;
}
__device__ __forceinline__ float bsp_at(const Bsp& r, int g) {
    int d = r.m - g;
    float v = 0.0f;
    v = (d == 3) ? r.w0 : v;
    v = (d == 2) ? r.w1 : v;
    v = (d == 1) ? r.w2 : v;
    v = (d == 0) ? r.w3 : v;
    return v;
}

// ---------------------------------------------------------------------------
// K2: layer-1 GEMM on mma.sync (validated round-4 structure).
// ---------------------------------------------------------------------------
__global__ void __launch_bounds__(256, 1) k2_mma(const float* __restrict__ x,
                                                const float* __restrict__ coef1,
                                                const float* __restrict__ sb1,
                                                const float* __restrict__ ssp1) {
    extern __shared__ __align__(16) char smem[];
    float* xs = (float*)(smem + SM_XS);

    const int tid  = threadIdx.x;
    const int lane = tid & 31;
    const int wid  = tid >> 5;
    const int wm   = wid >> 2;
    const int wn   = wid & 3;
    const int o0   = blockIdx.x * 128;
    const int split = blockIdx.y;
    const int i0   = split * IPC;

    for (int idx = tid; idx < B_ * IPC; idx += 256) {
        int b = idx / IPC, c = idx % IPC;
        xs[b * XS_PITCH + c] = x[b * IN_ + i0 + c];
    }

    float acc[4][4][4];
#pragma unroll
    for (int mi = 0; mi < 4; mi++)
#pragma unroll
        for (int ni = 0; ni < 4; ni++)
#pragma unroll
            for (int w = 0; w < 4; w++) acc[mi][ni][w] = 0.0f;

    float4 pc0[4], pc1[4];
    float  psp[4], psb[4];

    auto ldgA = [&](int ib) {
#pragma unroll
        for (int p = 0; p < 4; p++) {
            int q = tid + 256 * p;
            int o_l = q >> 3, ii = q & 7;
            int e = (o0 + o_l) * IN_ + ib + ii;
            pc0[p] = ((const float4*)coef1)[e * 2];
            pc1[p] = ((const float4*)coef1)[e * 2 + 1];
            psp[p] = ssp1[e];
            psb[p] = sb1[e];
        }
    };
    auto stsA = [&](uint32_t offA) {
        uint32_t* As = (uint32_t*)(smem + offA);
#pragma unroll
        for (int p = 0; p < 4; p++) {
            int q = tid + 256 * p;
            int o_l = q >> 3, ii = q & 7;
            float v[9] = { psp[p] * pc0[p].x, psp[p] * pc0[p].y, psp[p] * pc0[p].z,
                           psp[p] * pc0[p].w, psp[p] * pc1[p].x, psp[p] * pc1[p].y,
                           psp[p] * pc1[p].z, psp[p] * pc1[p].w, psb[p] };
            int mt = o_l >> 4, r = o_l & 15;
#pragma unroll
            for (int g = 0; g < 9; g++) {
                int kk = ii * 9 + g, ks = kk >> 3, kc = kk & 7;
                int idx = ((ks * 8 + mt) * 32 + (r & 7) * 4 + (kc & 3)) * 4
                          + ((kc >> 2) << 1) + (r >> 3);
                As[idx] = tf32r(v[g]);
            }
        }
    };
    auto prodB = [&](int coff, uint32_t offB) {
        uint32_t* Bs = (uint32_t*)(smem + offB);
#pragma unroll
        for (int p = 0; p < 4; p++) {
            int q = tid + 256 * p;
            int b = q & 127, ii = q >> 7;
            float xv = xs[b * XS_PITCH + coff + ii];
            Bsp bs = bspline4(xv);
            int nt = b >> 3, ln = (b & 7) * 4;
#pragma unroll
            for (int g = 0; g < 8; g++) {
                int kk = ii * 9 + g, ks = kk >> 3, kc = kk & 7;
                int idx = ((ks * 16 + nt) * 32 + ln + (kc & 3)) * 2 + (kc >> 2);
                Bs[idx] = tf32r(bsp_at(bs, g));
            }
            {
                int kk = ii * 9 + 8, ks = kk >> 3, kc = kk & 7;
                int idx = ((ks * 16 + nt) * 32 + ln + (kc & 3)) * 2 + (kc >> 2);
                Bs[idx] = tf32r(silu_f(xv));
            }
        }
    };
    auto consume = [&](uint32_t offA, uint32_t offB) {
        const float4* As = (const float4*)(smem + offA);
        const float2* Bs = (const float2*)(smem + offB);
#pragma unroll
        for (int ks = 0; ks < NKS; ks++) {
            uint32_t af[4][4], bf[4][2];
#pragma unroll
            for (int mi = 0; mi < 4; mi++) {
                float4 v = As[(ks * 8 + wm * 4 + mi) * 32 + lane];
                af[mi][0] = __float_as_uint(v.x); af[mi][1] = __float_as_uint(v.y);
                af[mi][2] = __float_as_uint(v.z); af[mi][3] = __float_as_uint(v.w);
            }
#pragma unroll
            for (int ni = 0; ni < 4; ni++) {
                float2 v = Bs[(ks * 16 + wn * 4 + ni) * 32 + lane];
                bf[ni][0] = __float_as_uint(v.x); bf[ni][1] = __float_as_uint(v.y);
            }
#pragma unroll
            for (int mi = 0; mi < 4; mi++)
#pragma unroll
                for (int ni = 0; ni < 4; ni++) mma8(acc[mi][ni], af[mi], bf[ni]);
        }
    };

    ldgA(i0);
    __syncthreads();
    prodB(0, SM_B0);
    stsA(SM_A0);
    __syncthreads();

    for (int t = 0; t < NCH; t++) {
        const uint32_t offA = (t & 1) ? SM_A1 : SM_A0;
        const uint32_t offB = (t & 1) ? SM_B1 : SM_B0;
        const uint32_t nfA  = (t & 1) ? SM_A0 : SM_A1;
        const uint32_t nfB  = (t & 1) ? SM_B0 : SM_B1;
        if (t + 1 < NCH) ldgA(i0 + (t + 1) * 8);
        consume(offA, offB);
        if (t + 1 < NCH) { stsA(nfA); prodB((t + 1) * 8, nfB); }
        __syncthreads();
    }

    // writeout: transpose through smem, coalesced float4 partial stores
    {
        float* S = (float*)(smem + SM_A0);
        const int r = lane >> 2, c = lane & 3;
#pragma unroll
        for (int mi = 0; mi < 4; mi++)
#pragma unroll
            for (int ni = 0; ni < 4; ni++)
#pragma unroll
                for (int w = 0; w < 4; w++) {
                    int o_l = (wm * 4 + mi) * 16 + r + 8 * (w >> 1);
                    int b_l = (wn * 4 + ni) * 8 + 2 * c + (w & 1);
                    S[b_l * SP + o_l] = acc[mi][ni][w];
                }
        __syncthreads();
        float* Y = g_Y1p + split * (B_ * H_);
#pragma unroll
        for (int p = 0; p < 16; p++) {
            int idx = tid + 256 * p;
            int bb = idx >> 5, o4 = idx & 31;
            float4 v = *(float4*)&S[bb * SP + o4 * 4];
            *(float4*)&Y[bb * H_ + o0 + o4 * 4] = v;
        }
    }
}

// ---------------------------------------------------------------------------
// K3a: split reduction, 256 CTAs. CTA c sums g_Y1p over 64 splits for 32
// consecutive float4 output slots. Warp w handles splits 8w..8w+7.
// ---------------------------------------------------------------------------
__global__ void __launch_bounds__(256) k3a_reduce() {
    __shared__ float4 sred[8][32];
    const int t = threadIdx.x, c = blockIdx.x;
    const int lane = t & 31, w = t >> 5;
    const int out = c * 32 + lane;          // float4 index into (b, o/4)
    const int b = out >> 6, o4 = out & 63;

    const float4* P = (const float4*)g_Y1p;
    float4 acc = make_float4(0.f, 0.f, 0.f, 0.f);
#pragma unroll
    for (int k = 0; k < 8; k++) {
        int s = w * 8 + k;
        float4 v = P[(s * B_ + b) * (H_ / 4) + o4];
        acc.x += v.x; acc.y += v.y; acc.z += v.z; acc.w += v.w;
    }
    sred[w][lane] = acc;
    __syncthreads();
    if (t < 32) {
        float4 a = sred[0][t];
#pragma unroll
        for (int j = 1; j < 8; j++) {
            float4 v = sred[j][t];
            a.x += v.x; a.y += v.y; a.z += v.z; a.w += v.w;
        }
        ((float4*)g_Y1)[c * 32 + t] = a;
    }
}

// ---------------------------------------------------------------------------
// K3b: layer 2. Grid 128 (batch), block 256 (hidden). Shfl reduction.
// ---------------------------------------------------------------------------
__global__ void __launch_bounds__(256) k3b_layer2(const float* __restrict__ coef2,
                                                 const float* __restrict__ sb2,
                                                 const float* __restrict__ ssp2,
                                                 float* __restrict__ out) {
    const int b = blockIdx.x;
    const int t = threadIdx.x;
    const int lane = t & 31, w = t >> 5;

    float h = selu_f(g_Y1[b * H_ + t]);
    Bsp bs = bspline4(h);
    float f0 = silu_f(h);
    float fb[8];
#pragma unroll
    for (int g = 0; g < 8; g++) fb[g] = bsp_at(bs, g);

    __shared__ float red[OUT_ * 8];
    float val[OUT_];
#pragma unroll
    for (int o = 0; o < OUT_; o++) {
        int e = o * H_ + t;
        float4 c0 = ((const float4*)coef2)[e * 2];
        float4 c1 = ((const float4*)coef2)[e * 2 + 1];
        float sp = ssp2[e];
        float spline = fb[0] * c0.x + fb[1] * c0.y + fb[2] * c0.z + fb[3] * c0.w
                     + fb[4] * c1.x + fb[5] * c1.y + fb[6] * c1.z + fb[7] * c1.w;
        val[o] = sb2[e] * f0 + sp * spline;
    }
#pragma unroll
    for (int o = 0; o < OUT_; o++) {
#pragma unroll
        for (int off = 16; off > 0; off >>= 1)
            val[o] += __shfl_down_sync(0xFFFFFFFFu, val[o], off);
    }
    if (lane == 0) {
#pragma unroll
        for (int o = 0; o < OUT_; o++) red[o * 8 + w] = val[o];
    }
    __syncthreads();
    if (t < OUT_) {
        float s = 0.0f;
#pragma unroll
        for (int j = 0; j < 8; j++) s += red[t * 8 + j];
        out[b * OUT_ + t] = s;
    }
}

// ---------------------------------------------------------------------------
extern "C" void kernel_launch(void* const* d_in, const int* in_sizes, int n_in,
                              void* d_out, int out_size) {
    const float* x     = (const float*)d_in[0];
    const float* coef1 = (const float*)d_in[1];
    const float* sb1   = (const float*)d_in[2];
    const float* ssp1  = (const float*)d_in[3];
    const float* coef2 = (const float*)d_in[4];
    const float* sb2   = (const float*)d_in[5];
    const float* ssp2  = (const float*)d_in[6];
    float* out = (float*)d_out;

    cudaFuncSetAttribute(k2_mma, cudaFuncAttributeMaxDynamicSharedMemorySize, SMEM_TOTAL);
    k2_mma<<<dim3(2, KSPLIT), 256, SMEM_TOTAL>>>(x, coef1, sb1, ssp1);
    k3a_reduce<<<(B_ * H_) / (32 * 4), 256>>>();
    k3b_layer2<<<B_, 256>>>(coef2, sb2, ssp2, out);
}